// round 1
// baseline (speedup 1.0000x reference)
#include <cuda_runtime.h>

// Problem constants
#define BB 4
#define SS 4096
#define HH 1024
#define MT (BB * SS)          // 16384 total rows
#define QT (SS / 128)         // 32 query tiles per batch
#define NW 5                  // window tiles (window = 640 keys incl. diagonal tile)
#define WK (NW * 128)         // 640
#define LOG2G (-0.04580369f)  // log2(0.96875)

// Scratch (allocation-free rule: __device__ globals)
__device__ float g_q[(size_t)MT * HH];
__device__ float g_k[(size_t)MT * HH];
__device__ float g_v[(size_t)MT * HH];
__device__ float g_s[(size_t)BB * QT * 128 * WK];  // [b][qtile][qi(128)][k(640)]

// ---------------------------------------------------------------------------
// Projection GEMM (NT): C[m,n] = sum_k A[m,k] * W[n,k] (+ bias[n])
// M=16384, N=1024, K=1024. 128x128 block, BK=16, 256 threads, 8x8 per thread.
// which: 0 -> g_q (bias), 1 -> g_k (bias), 2 -> g_v (no bias)
// ---------------------------------------------------------------------------
__global__ __launch_bounds__(256) void proj_gemm(
    const float* __restrict__ A, const float* __restrict__ W,
    const float* __restrict__ bias, int which)
{
    const int K = HH, N = HH;
    __shared__ float As[16][128];
    __shared__ float Bs[16][128];
    int m0 = blockIdx.y * 128;
    int n0 = blockIdx.x * 128;
    int tid = threadIdx.x;
    int tx = tid & 15, ty = tid >> 4;
    int lr = tid >> 2;          // 0..63
    int lc = (tid & 3) << 2;    // 0,4,8,12

    float acc[8][8];
    #pragma unroll
    for (int i = 0; i < 8; i++)
        #pragma unroll
        for (int j = 0; j < 8; j++) acc[i][j] = 0.f;

    for (int k0 = 0; k0 < K; k0 += 16) {
        #pragma unroll
        for (int r = 0; r < 2; r++) {
            int m = lr + r * 64;
            float4 va = *(const float4*)(A + (size_t)(m0 + m) * K + k0 + lc);
            As[lc + 0][m] = va.x; As[lc + 1][m] = va.y;
            As[lc + 2][m] = va.z; As[lc + 3][m] = va.w;
            float4 vb = *(const float4*)(W + (size_t)(n0 + m) * K + k0 + lc);
            Bs[lc + 0][m] = vb.x; Bs[lc + 1][m] = vb.y;
            Bs[lc + 2][m] = vb.z; Bs[lc + 3][m] = vb.w;
        }
        __syncthreads();
        #pragma unroll
        for (int kk = 0; kk < 16; kk++) {
            float a[8], b[8];
            *(float4*)(a + 0) = *(const float4*)&As[kk][ty * 8];
            *(float4*)(a + 4) = *(const float4*)&As[kk][ty * 8 + 4];
            *(float4*)(b + 0) = *(const float4*)&Bs[kk][tx * 8];
            *(float4*)(b + 4) = *(const float4*)&Bs[kk][tx * 8 + 4];
            #pragma unroll
            for (int i = 0; i < 8; i++)
                #pragma unroll
                for (int j = 0; j < 8; j++)
                    acc[i][j] += a[i] * b[j];
        }
        __syncthreads();
    }

    float* C = (which == 0) ? g_q : (which == 1) ? g_k : g_v;
    bool has_bias = (which != 2);
    #pragma unroll
    for (int i = 0; i < 8; i++) {
        int m = m0 + ty * 8 + i;
        #pragma unroll
        for (int j = 0; j < 8; j += 4) {
            int n = n0 + tx * 8 + j;
            float4 o;
            o.x = acc[i][j + 0] + (has_bias ? bias[n + 0] : 0.f);
            o.y = acc[i][j + 1] + (has_bias ? bias[n + 1] : 0.f);
            o.z = acc[i][j + 2] + (has_bias ? bias[n + 2] : 0.f);
            o.w = acc[i][j + 3] + (has_bias ? bias[n + 3] : 0.f);
            *(float4*)(C + (size_t)m * N + n) = o;
        }
    }
}

// ---------------------------------------------------------------------------
// Windowed decayed scores: S[b,qt][qi][w*128+kj] = (q_i . k_j) * gamma^(i-j)
// block = (w, qtile, batch); 128x128x1024 NT GEMM + decay epilogue.
// ---------------------------------------------------------------------------
__global__ __launch_bounds__(256) void score_gemm()
{
    int w  = blockIdx.x;   // 0..NW-1
    int qt = blockIdx.y;   // 0..31
    int b  = blockIdx.z;   // 0..3
    int i0 = qt * 128;
    int j0 = i0 + (w - (NW - 1)) * 128;

    float* Sout = g_s + (size_t)(b * QT + qt) * 128 * WK;
    int tid = threadIdx.x;
    int tx = tid & 15, ty = tid >> 4;

    if (j0 < 0) {  // out-of-range window tile: zero-fill
        #pragma unroll
        for (int i = 0; i < 8; i++)
            #pragma unroll
            for (int j = 0; j < 8; j += 4)
                *(float4*)&Sout[(size_t)(ty * 8 + i) * WK + w * 128 + tx * 8 + j] =
                    make_float4(0.f, 0.f, 0.f, 0.f);
        return;
    }

    const float* A  = g_q + ((size_t)b * SS + i0) * HH;
    const float* Bp = g_k + ((size_t)b * SS + j0) * HH;

    __shared__ float As[16][128];
    __shared__ float Bs[16][128];
    int lr = tid >> 2;
    int lc = (tid & 3) << 2;

    float acc[8][8];
    #pragma unroll
    for (int i = 0; i < 8; i++)
        #pragma unroll
        for (int j = 0; j < 8; j++) acc[i][j] = 0.f;

    for (int k0 = 0; k0 < HH; k0 += 16) {
        #pragma unroll
        for (int r = 0; r < 2; r++) {
            int m = lr + r * 64;
            float4 va = *(const float4*)(A + (size_t)m * HH + k0 + lc);
            As[lc + 0][m] = va.x; As[lc + 1][m] = va.y;
            As[lc + 2][m] = va.z; As[lc + 3][m] = va.w;
            float4 vb = *(const float4*)(Bp + (size_t)m * HH + k0 + lc);
            Bs[lc + 0][m] = vb.x; Bs[lc + 1][m] = vb.y;
            Bs[lc + 2][m] = vb.z; Bs[lc + 3][m] = vb.w;
        }
        __syncthreads();
        #pragma unroll
        for (int kk = 0; kk < 16; kk++) {
            float a[8], bb[8];
            *(float4*)(a  + 0) = *(const float4*)&As[kk][ty * 8];
            *(float4*)(a  + 4) = *(const float4*)&As[kk][ty * 8 + 4];
            *(float4*)(bb + 0) = *(const float4*)&Bs[kk][tx * 8];
            *(float4*)(bb + 4) = *(const float4*)&Bs[kk][tx * 8 + 4];
            #pragma unroll
            for (int i = 0; i < 8; i++)
                #pragma unroll
                for (int j = 0; j < 8; j++)
                    acc[i][j] += a[i] * bb[j];
        }
        __syncthreads();
    }

    // Decay epilogue: weight = gamma^(i-j), 0 if j > i
    #pragma unroll
    for (int i = 0; i < 8; i++) {
        int m = ty * 8 + i;
        #pragma unroll
        for (int j = 0; j < 8; j += 4) {
            int n = tx * 8 + j;
            float4 o;
            float* ov = &o.x;
            #pragma unroll
            for (int u = 0; u < 4; u++) {
                int d = (i0 + m) - (j0 + n + u);
                float wgt = (d < 0) ? 0.f : exp2f(LOG2G * (float)d);
                ov[u] = acc[i][j + u] * wgt;
            }
            *(float4*)&Sout[(size_t)m * WK + w * 128 + n] = o;
        }
    }
}

// ---------------------------------------------------------------------------
// Output GEMM (NN, banded): O[b, i0+qi, n] = sum_{k=0..639} S[qi][k] * V[jbase+k, n]
// block = (nchunk, qtile, batch). jbase may be negative; S is zero there.
// ---------------------------------------------------------------------------
__global__ __launch_bounds__(256) void out_gemm(float* __restrict__ out)
{
    int nc = blockIdx.x;   // 0..7
    int qt = blockIdx.y;   // 0..31
    int b  = blockIdx.z;   // 0..3
    int i0 = qt * 128;
    int n0 = nc * 128;
    int jbase = i0 - (NW - 1) * 128;

    const float* A = g_s + (size_t)(b * QT + qt) * 128 * WK;  // [128][640]

    __shared__ float As[16][128];
    __shared__ float Bs[16][128];
    int tid = threadIdx.x;
    int tx = tid & 15, ty = tid >> 4;
    int lr = tid >> 2;
    int lc = (tid & 3) << 2;
    int bk_row = tid >> 5;          // 0..7
    int bk_col = (tid & 31) << 2;   // 0..124

    float acc[8][8];
    #pragma unroll
    for (int i = 0; i < 8; i++)
        #pragma unroll
        for (int j = 0; j < 8; j++) acc[i][j] = 0.f;

    for (int k0 = 0; k0 < WK; k0 += 16) {
        #pragma unroll
        for (int r = 0; r < 2; r++) {
            int m = lr + r * 64;
            float4 va = *(const float4*)(A + (size_t)m * WK + k0 + lc);
            As[lc + 0][m] = va.x; As[lc + 1][m] = va.y;
            As[lc + 2][m] = va.z; As[lc + 3][m] = va.w;
        }
        #pragma unroll
        for (int r = 0; r < 2; r++) {
            int kk = bk_row + r * 8;
            int j = jbase + k0 + kk;
            if (j < 0) j = 0;  // S is zero for these k, value irrelevant
            float4 vb = *(const float4*)(g_v + ((size_t)b * SS + j) * HH + n0 + bk_col);
            *(float4*)&Bs[kk][bk_col] = vb;
        }
        __syncthreads();
        #pragma unroll
        for (int kk = 0; kk < 16; kk++) {
            float a[8], bb[8];
            *(float4*)(a  + 0) = *(const float4*)&As[kk][ty * 8];
            *(float4*)(a  + 4) = *(const float4*)&As[kk][ty * 8 + 4];
            *(float4*)(bb + 0) = *(const float4*)&Bs[kk][tx * 8];
            *(float4*)(bb + 4) = *(const float4*)&Bs[kk][tx * 8 + 4];
            #pragma unroll
            for (int i = 0; i < 8; i++)
                #pragma unroll
                for (int j = 0; j < 8; j++)
                    acc[i][j] += a[i] * bb[j];
        }
        __syncthreads();
    }

    #pragma unroll
    for (int i = 0; i < 8; i++) {
        int m = i0 + ty * 8 + i;
        #pragma unroll
        for (int j = 0; j < 8; j += 4) {
            int n = n0 + tx * 8 + j;
            float4 o;
            o.x = acc[i][j + 0]; o.y = acc[i][j + 1];
            o.z = acc[i][j + 2]; o.w = acc[i][j + 3];
            *(float4*)(out + ((size_t)b * SS + m) * HH + n) = o;
        }
    }
}

// ---------------------------------------------------------------------------
extern "C" void kernel_launch(void* const* d_in, const int* in_sizes, int n_in,
                              void* d_out, int out_size)
{
    const float* x  = (const float*)d_in[0];
    const float* Wq = (const float*)d_in[1];
    const float* bq = (const float*)d_in[2];
    const float* Wk = (const float*)d_in[3];
    const float* bk = (const float*)d_in[4];
    const float* Wv = (const float*)d_in[5];
    float* out = (float*)d_out;

    dim3 gproj(HH / 128, MT / 128);  // (8, 128)
    proj_gemm<<<gproj, 256>>>(x, Wq, bq, 0);
    proj_gemm<<<gproj, 256>>>(x, Wk, bk, 1);
    proj_gemm<<<gproj, 256>>>(x, Wv, nullptr, 2);

    dim3 gscore(NW, QT, BB);         // (5, 32, 4)
    score_gemm<<<gscore, 256>>>();

    dim3 gout(HH / 128, QT, BB);     // (8, 32, 4)
    out_gemm<<<gout, 256>>>(out);
}

// round 3
// speedup vs baseline: 2.7377x; 2.7377x over previous
#include <cuda_runtime.h>
#include <cuda_bf16.h>
#include <stdint.h>

// ---------------- problem constants ----------------
#define BB 4
#define SS 4096
#define HH 1024
#define QT 32
#define NW 5
#define WK 640
#define LOG2G (-0.04580368961312758f)

// ---------------- smem layout ----------------
// Tiles stored as [128 rows][32 k] bf16, row stride padded to 80 bytes
// (64 data + 16 pad) -> conflict-free ldmatrix & reasonable STS.
#define RST 80
#define TILE_B (128 * RST)      // 10240
#define OFF_AHI 0
#define OFF_ALO (1 * TILE_B)
#define OFF_BHI (2 * TILE_B)
#define OFF_BLO (3 * TILE_B)
#define STG_B (4 * TILE_B)      // 40960 per stage
#define SMEM_TOTAL (2 * STG_B)  // 81920

// ---------------- device scratch ----------------
__device__ __align__(16) float g_q[(size_t)BB * SS * HH];
__device__ __align__(16) float g_k[(size_t)BB * SS * HH];
__device__ __align__(16) float g_v[(size_t)BB * SS * HH];
__device__ __align__(16) __nv_bfloat16 g_shi[(size_t)BB * QT * 128 * WK];
__device__ __align__(16) __nv_bfloat16 g_slo[(size_t)BB * QT * 128 * WK];

// ---------------- helpers ----------------
__device__ __forceinline__ uint32_t smem_u32(const void* p) {
    uint32_t a;
    asm("{ .reg .u64 t; cvta.to.shared.u64 t, %1; cvt.u32.u64 %0, t; }"
        : "=r"(a) : "l"(p));
    return a;
}
__device__ __forceinline__ void ldsm_x4(uint32_t* r, uint32_t addr) {
    asm volatile("ldmatrix.sync.aligned.m8n8.x4.shared.b16 {%0,%1,%2,%3}, [%4];"
                 : "=r"(r[0]), "=r"(r[1]), "=r"(r[2]), "=r"(r[3]) : "r"(addr));
}
__device__ __forceinline__ void ldsm_x2(uint32_t* r, uint32_t addr) {
    asm volatile("ldmatrix.sync.aligned.m8n8.x2.shared.b16 {%0,%1}, [%2];"
                 : "=r"(r[0]), "=r"(r[1]) : "r"(addr));
}
__device__ __forceinline__ void mma16816(float* d, const uint32_t* a, const uint32_t* b) {
    asm volatile(
        "mma.sync.aligned.m16n8k16.row.col.f32.bf16.bf16.f32 "
        "{%0,%1,%2,%3}, {%4,%5,%6,%7}, {%8,%9}, {%0,%1,%2,%3};"
        : "+f"(d[0]), "+f"(d[1]), "+f"(d[2]), "+f"(d[3])
        : "r"(a[0]), "r"(a[1]), "r"(a[2]), "r"(a[3]), "r"(b[0]), "r"(b[1]));
}

// Exact mask-split of two fp32 into bf16x2 hi (truncated) + bf16x2 lo (residual).
__device__ __forceinline__ void split2(float x, float y, uint32_t& hi, uint32_t& lo) {
    uint32_t xu = __float_as_uint(x), yu = __float_as_uint(y);
    hi = __byte_perm(xu, yu, 0x7632);  // {bf16(x_trunc), bf16(y_trunc)}
    float hx = __uint_as_float(xu & 0xFFFF0000u);
    float hy = __uint_as_float(yu & 0xFFFF0000u);
    __nv_bfloat162 l = __float22bfloat162_rn(make_float2(x - hx, y - hy));
    lo = reinterpret_cast<uint32_t&>(l);
}
__device__ __forceinline__ void split_f4_sts(char* smhi, char* smlo, uint32_t off, float4 v) {
    uint2 h, l;
    split2(v.x, v.y, h.x, l.x);
    split2(v.z, v.w, h.y, l.y);
    *reinterpret_cast<uint2*>(smhi + off) = h;
    *reinterpret_cast<uint2*>(smlo + off) = l;
}

// One K-chunk (32) of warp-level MMAs: 3 split terms, warp tile 32m x 64n.
__device__ __forceinline__ void compute_chunk(uint32_t st, int wm, int wn, int lane,
                                              float (*d)[4]) {
    #pragma unroll
    for (int ks = 0; ks < 2; ks++) {
        uint32_t arow = (uint32_t)(wm * 32 + (lane & 15)) * RST +
                        (uint32_t)(((lane >> 4) & 1) * 16 + ks * 32);
        uint32_t ah[8], al[8];
        ldsm_x4(ah,     st + OFF_AHI + arow);
        ldsm_x4(ah + 4, st + OFF_AHI + arow + 16 * RST);
        ldsm_x4(al,     st + OFF_ALO + arow);
        ldsm_x4(al + 4, st + OFF_ALO + arow + 16 * RST);
        #pragma unroll
        for (int nt = 0; nt < 8; nt++) {
            uint32_t brow = (uint32_t)(wn * 64 + nt * 8 + (lane & 7)) * RST +
                            (uint32_t)(((lane >> 3) & 1) * 16 + ks * 32);
            uint32_t bh[2], bl[2];
            ldsm_x2(bh, st + OFF_BHI + brow);
            ldsm_x2(bl, st + OFF_BLO + brow);
            mma16816(d[0 * 8 + nt], ah,     bh);
            mma16816(d[1 * 8 + nt], ah + 4, bh);
            mma16816(d[0 * 8 + nt], ah,     bl);
            mma16816(d[1 * 8 + nt], ah + 4, bl);
            mma16816(d[0 * 8 + nt], al,     bh);
            mma16816(d[1 * 8 + nt], al + 4, bh);
        }
    }
}

// fp32 K-major tile loader: 128 rows x 32 k. Each thread: 4 float4.
__device__ __forceinline__ void lda_f32(const float* __restrict__ src, int ld, int k0,
                                        int tid, float4* v) {
    int r = tid >> 3, c = tid & 7;
    #pragma unroll
    for (int h = 0; h < 4; h++)
        v[h] = *reinterpret_cast<const float4*>(src + (size_t)(r + 32 * h) * ld + k0 + c * 4);
}
__device__ __forceinline__ void sts_f32(char* smhi, char* smlo, int tid, const float4* v) {
    int r = tid >> 3, c = tid & 7;
    #pragma unroll
    for (int h = 0; h < 4; h++)
        split_f4_sts(smhi, smlo, (uint32_t)(r + 32 * h) * RST + c * 8, v[h]);
}

// ---------------- kernel 1: projections (C = A * W^T + bias) ----------------
__global__ __launch_bounds__(256) void proj_hmma(const float* __restrict__ A,
                                                 const float* __restrict__ W,
                                                 const float* __restrict__ bias, int which) {
    extern __shared__ char sm[];
    uint32_t smb = smem_u32(sm);
    int tid = threadIdx.x, lane = tid & 31, wid = tid >> 5;
    int wm = wid & 3, wn = wid >> 2;
    int m0 = blockIdx.y * 128, n0 = blockIdx.x * 128;
    const float* Ab = A + (size_t)m0 * HH;
    const float* Bb = W + (size_t)n0 * HH;

    float d[16][4];
    #pragma unroll
    for (int i = 0; i < 16; i++)
        #pragma unroll
        for (int j = 0; j < 4; j++) d[i][j] = 0.f;

    float4 va[4], vb[4];
    lda_f32(Ab, HH, 0, tid, va);
    lda_f32(Bb, HH, 0, tid, vb);
    sts_f32(sm + OFF_AHI, sm + OFF_ALO, tid, va);
    sts_f32(sm + OFF_BHI, sm + OFF_BLO, tid, vb);
    __syncthreads();

    const int NC = HH / 32;  // 32
    for (int c = 0; c < NC; c++) {
        if (c + 1 < NC) {
            lda_f32(Ab, HH, (c + 1) * 32, tid, va);
            lda_f32(Bb, HH, (c + 1) * 32, tid, vb);
        }
        compute_chunk(smb + (uint32_t)(c & 1) * STG_B, wm, wn, lane, d);
        if (c + 1 < NC) {
            char* stn = sm + ((c + 1) & 1) * STG_B;
            sts_f32(stn + OFF_AHI, stn + OFF_ALO, tid, va);
            sts_f32(stn + OFF_BHI, stn + OFF_BLO, tid, vb);
        }
        __syncthreads();
    }

    float* C = (which == 0) ? g_q : (which == 1) ? g_k : g_v;
    int tq = lane >> 2, tr = lane & 3;
    #pragma unroll
    for (int mt = 0; mt < 2; mt++)
        #pragma unroll
        for (int nt = 0; nt < 8; nt++) {
            int ml = wm * 32 + mt * 16 + tq;
            int n = n0 + wn * 64 + nt * 8 + tr * 2;
            float b0 = 0.f, b1 = 0.f;
            if (bias) { b0 = bias[n]; b1 = bias[n + 1]; }
            float* dd = d[mt * 8 + nt];
            *reinterpret_cast<float2*>(C + (size_t)(m0 + ml) * HH + n) =
                make_float2(dd[0] + b0, dd[1] + b1);
            *reinterpret_cast<float2*>(C + (size_t)(m0 + ml + 8) * HH + n) =
                make_float2(dd[2] + b0, dd[3] + b1);
        }
}

// ---------------- kernel 2: windowed decayed scores ----------------
__global__ __launch_bounds__(256) void score_hmma() {
    int w = blockIdx.x, qt = blockIdx.y, b = blockIdx.z;
    int i0 = qt * 128, j0 = i0 + (w - (NW - 1)) * 128;
    int tid = threadIdx.x, lane = tid & 31, wid = tid >> 5;
    size_t tile = ((size_t)(b * QT + qt)) * 128 * WK;

    if (j0 < 0) {  // zero-fill out-of-range window tiles
        for (int i = tid; i < 128 * 16; i += 256) {
            int row = i >> 4, q = i & 15;
            size_t o = tile + (size_t)row * WK + w * 128 + q * 8;
            *reinterpret_cast<uint4*>(g_shi + o) = make_uint4(0, 0, 0, 0);
            *reinterpret_cast<uint4*>(g_slo + o) = make_uint4(0, 0, 0, 0);
        }
        return;
    }

    extern __shared__ char sm[];
    uint32_t smb = smem_u32(sm);
    int wm = wid & 3, wn = wid >> 2;
    const float* Ab = g_q + ((size_t)b * SS + i0) * HH;
    const float* Bb = g_k + ((size_t)b * SS + j0) * HH;

    float d[16][4];
    #pragma unroll
    for (int i = 0; i < 16; i++)
        #pragma unroll
        for (int j = 0; j < 4; j++) d[i][j] = 0.f;

    float4 va[4], vb[4];
    lda_f32(Ab, HH, 0, tid, va);
    lda_f32(Bb, HH, 0, tid, vb);
    sts_f32(sm + OFF_AHI, sm + OFF_ALO, tid, va);
    sts_f32(sm + OFF_BHI, sm + OFF_BLO, tid, vb);
    __syncthreads();

    const int NC = HH / 32;
    for (int c = 0; c < NC; c++) {
        if (c + 1 < NC) {
            lda_f32(Ab, HH, (c + 1) * 32, tid, va);
            lda_f32(Bb, HH, (c + 1) * 32, tid, vb);
        }
        compute_chunk(smb + (uint32_t)(c & 1) * STG_B, wm, wn, lane, d);
        if (c + 1 < NC) {
            char* stn = sm + ((c + 1) & 1) * STG_B;
            sts_f32(stn + OFF_AHI, stn + OFF_ALO, tid, va);
            sts_f32(stn + OFF_BHI, stn + OFF_BLO, tid, vb);
        }
        __syncthreads();
    }

    // decay + split epilogue
    int tq = lane >> 2, tr = lane & 3;
    #pragma unroll
    for (int mt = 0; mt < 2; mt++)
        #pragma unroll
        for (int nt = 0; nt < 8; nt++) {
            int ncol = wn * 64 + nt * 8 + tr * 2;
            float* dd = d[mt * 8 + nt];
            #pragma unroll
            for (int half = 0; half < 2; half++) {
                int ml = wm * 32 + mt * 16 + tq + half * 8;
                int i = i0 + ml;
                int d0 = i - (j0 + ncol), d1 = i - (j0 + ncol + 1);
                float w0 = (d0 < 0) ? 0.f : exp2f(LOG2G * (float)d0);
                float w1 = (d1 < 0) ? 0.f : exp2f(LOG2G * (float)d1);
                float v0 = dd[half * 2 + 0] * w0;
                float v1 = dd[half * 2 + 1] * w1;
                uint32_t hi, lo;
                split2(v0, v1, hi, lo);
                size_t o = tile + (size_t)ml * WK + w * 128 + ncol;
                *reinterpret_cast<uint32_t*>(g_shi + o) = hi;
                *reinterpret_cast<uint32_t*>(g_slo + o) = lo;
            }
        }
}

// ---------------- kernel 3: banded output GEMM O = S * V ----------------
__global__ __launch_bounds__(256) void out_hmma(float* __restrict__ out) {
    int nc = blockIdx.x, qt = blockIdx.y, b = blockIdx.z;
    int i0 = qt * 128, n0 = nc * 128, jbase = i0 - (NW - 1) * 128;
    int tid = threadIdx.x, lane = tid & 31, wid = tid >> 5;
    int wm = wid & 3, wn = wid >> 2;
    size_t tile = ((size_t)(b * QT + qt)) * 128 * WK;
    const __nv_bfloat16* Sh = g_shi + tile;
    const __nv_bfloat16* Sl = g_slo + tile;
    const float* Vb = g_v + (size_t)b * SS * HH;

    extern __shared__ char sm[];
    uint32_t smb = smem_u32(sm);

    float d[16][4];
    #pragma unroll
    for (int i = 0; i < 16; i++)
        #pragma unroll
        for (int j = 0; j < 4; j++) d[i][j] = 0.f;

    // staging regs
    uint4 sh[2], sl[2];
    float4 vv[4];
    int sr = tid >> 2, sc = tid & 3;       // S: rows sr, sr+64; 16B piece sc
    int vj = tid >> 3, vc = tid & 7;       // V: k-row vj, f4 pieces vc+8q

    auto ldS = [&](int k0) {
        #pragma unroll
        for (int h = 0; h < 2; h++) {
            sh[h] = *reinterpret_cast<const uint4*>(Sh + (size_t)(sr + 64 * h) * WK + k0 + sc * 8);
            sl[h] = *reinterpret_cast<const uint4*>(Sl + (size_t)(sr + 64 * h) * WK + k0 + sc * 8);
        }
    };
    auto ldV = [&](int k0) {
        int j = jbase + k0 + vj;
        if (j < 0) j = 0;  // S is zero there
        const float* vr = Vb + (size_t)j * HH + n0;
        #pragma unroll
        for (int q = 0; q < 4; q++)
            vv[q] = *reinterpret_cast<const float4*>(vr + (vc + 8 * q) * 4);
    };
    auto stS = [&](char* st) {
        #pragma unroll
        for (int h = 0; h < 2; h++) {
            uint32_t off = (uint32_t)(sr + 64 * h) * RST + sc * 16;
            *reinterpret_cast<uint4*>(st + OFF_AHI + off) = sh[h];
            *reinterpret_cast<uint4*>(st + OFF_ALO + off) = sl[h];
        }
    };
    auto stV = [&](char* st) {
        #pragma unroll
        for (int q = 0; q < 4; q++) {
            int n = (vc + 8 * q) * 4;
            float xs[4] = {vv[q].x, vv[q].y, vv[q].z, vv[q].w};
            #pragma unroll
            for (int u = 0; u < 4; u++) {
                uint32_t xu = __float_as_uint(xs[u]);
                float hf = __uint_as_float(xu & 0xFFFF0000u);
                __nv_bfloat16 lb = __float2bfloat16(xs[u] - hf);
                uint32_t off = (uint32_t)(n + u) * RST + vj * 2;
                *reinterpret_cast<uint16_t*>(st + OFF_BHI + off) = (uint16_t)(xu >> 16);
                *reinterpret_cast<uint16_t*>(st + OFF_BLO + off) =
                    reinterpret_cast<uint16_t&>(lb);
            }
        }
    };

    ldS(0); ldV(0);
    stS(sm); stV(sm);
    __syncthreads();

    const int NC = WK / 32;  // 20
    for (int c = 0; c < NC; c++) {
        if (c + 1 < NC) { ldS((c + 1) * 32); ldV((c + 1) * 32); }
        compute_chunk(smb + (uint32_t)(c & 1) * STG_B, wm, wn, lane, d);
        if (c + 1 < NC) {
            char* stn = sm + ((c + 1) & 1) * STG_B;
            stS(stn); stV(stn);
        }
        __syncthreads();
    }

    int tq = lane >> 2, tr = lane & 3;
    #pragma unroll
    for (int mt = 0; mt < 2; mt++)
        #pragma unroll
        for (int nt = 0; nt < 8; nt++) {
            int ml = wm * 32 + mt * 16 + tq;
            int n = n0 + wn * 64 + nt * 8 + tr * 2;
            float* dd = d[mt * 8 + nt];
            *reinterpret_cast<float2*>(out + ((size_t)b * SS + i0 + ml) * HH + n) =
                make_float2(dd[0], dd[1]);
            *reinterpret_cast<float2*>(out + ((size_t)b * SS + i0 + ml + 8) * HH + n) =
                make_float2(dd[2], dd[3]);
        }
}

// ---------------- host launcher ----------------
extern "C" void kernel_launch(void* const* d_in, const int* in_sizes, int n_in,
                              void* d_out, int out_size) {
    const float* x  = (const float*)d_in[0];
    const float* Wq = (const float*)d_in[1];
    const float* bq = (const float*)d_in[2];
    const float* Wk = (const float*)d_in[3];
    const float* bk = (const float*)d_in[4];
    const float* Wv = (const float*)d_in[5];
    float* out = (float*)d_out;

    cudaFuncSetAttribute(proj_hmma, cudaFuncAttributeMaxDynamicSharedMemorySize, SMEM_TOTAL);
    cudaFuncSetAttribute(score_hmma, cudaFuncAttributeMaxDynamicSharedMemorySize, SMEM_TOTAL);
    cudaFuncSetAttribute(out_hmma, cudaFuncAttributeMaxDynamicSharedMemorySize, SMEM_TOTAL);

    dim3 gproj(HH / 128, (BB * SS) / 128);  // (8, 128)
    proj_hmma<<<gproj, 256, SMEM_TOTAL>>>(x, Wq, bq, 0);
    proj_hmma<<<gproj, 256, SMEM_TOTAL>>>(x, Wk, bk, 1);
    proj_hmma<<<gproj, 256, SMEM_TOTAL>>>(x, Wv, nullptr, 2);

    dim3 gscore(NW, QT, BB);  // (5, 32, 4)
    score_hmma<<<gscore, 256, SMEM_TOTAL>>>();

    dim3 gout(HH / 128, QT, BB);  // (8, 32, 4)
    out_hmma<<<gout, 256, SMEM_TOTAL>>>(out);
}

// round 4
// speedup vs baseline: 2.7510x; 1.0049x over previous
#include <cuda_runtime.h>
#include <cuda_bf16.h>
#include <stdint.h>

// ---------------- problem constants ----------------
#define BB 4
#define SS 4096
#define HH 1024
#define MT (BB * SS)
#define QT 32
#define NW 5
#define WK 640
#define LOG2G (-0.04580368961312758f)

// ---------------- smem layout: XOR-swizzled 64B rows ----------------
// tile = 128 rows x 32 bf16 (64B). phys(row,cu16) = row*64 + ((cu ^ ((row>>1)&3))*16)
#define OFF_AHI 0
#define OFF_ALO 8192
#define OFF_BHI 16384
#define OFF_BLO 24576
#define STG_B 32768
#define NSTG 3
#define SMEM_TOTAL (NSTG * STG_B)  // 98304

// ---------------- device scratch ----------------
__device__ __align__(16) __nv_bfloat16 g_xhi[(size_t)MT * HH];
__device__ __align__(16) __nv_bfloat16 g_xlo[(size_t)MT * HH];
__device__ __align__(16) __nv_bfloat16 g_whi[3][(size_t)HH * HH];
__device__ __align__(16) __nv_bfloat16 g_wlo[3][(size_t)HH * HH];
__device__ __align__(16) __nv_bfloat16 g_qhi[(size_t)MT * HH];
__device__ __align__(16) __nv_bfloat16 g_qlo[(size_t)MT * HH];
__device__ __align__(16) __nv_bfloat16 g_khi[(size_t)MT * HH];
__device__ __align__(16) __nv_bfloat16 g_klo[(size_t)MT * HH];
__device__ __align__(16) float g_v[(size_t)MT * HH];
__device__ __align__(16) __nv_bfloat16 g_vthi[(size_t)MT * HH];  // [b][h][s]
__device__ __align__(16) __nv_bfloat16 g_vtlo[(size_t)MT * HH];
__device__ __align__(16) __nv_bfloat16 g_shi[(size_t)BB * QT * 128 * WK];
__device__ __align__(16) __nv_bfloat16 g_slo[(size_t)BB * QT * 128 * WK];

// ---------------- helpers ----------------
__device__ __forceinline__ uint32_t smem_u32(const void* p) {
    uint32_t a;
    asm("{ .reg .u64 t; cvta.to.shared.u64 t, %1; cvt.u32.u64 %0, t; }"
        : "=r"(a) : "l"(p));
    return a;
}
__device__ __forceinline__ uint32_t swz(uint32_t row, uint32_t cu) {
    return row * 64u + ((cu ^ ((row >> 1) & 3u)) << 4);
}
#define CP16(dst, src) \
    asm volatile("cp.async.cg.shared.global [%0], [%1], 16;" :: "r"(dst), "l"(src))
#define CP_COMMIT() asm volatile("cp.async.commit_group;" ::: "memory")
#define CP_WAIT(n)  asm volatile("cp.async.wait_group %0;" :: "n"(n) : "memory")

__device__ __forceinline__ void ldsm_x4(uint32_t* r, uint32_t addr) {
    asm volatile("ldmatrix.sync.aligned.m8n8.x4.shared.b16 {%0,%1,%2,%3}, [%4];"
                 : "=r"(r[0]), "=r"(r[1]), "=r"(r[2]), "=r"(r[3]) : "r"(addr));
}
__device__ __forceinline__ void mma16816(float* d, const uint32_t* a, const uint32_t* b) {
    asm volatile(
        "mma.sync.aligned.m16n8k16.row.col.f32.bf16.bf16.f32 "
        "{%0,%1,%2,%3}, {%4,%5,%6,%7}, {%8,%9}, {%0,%1,%2,%3};"
        : "+f"(d[0]), "+f"(d[1]), "+f"(d[2]), "+f"(d[3])
        : "r"(a[0]), "r"(a[1]), "r"(a[2]), "r"(a[3]), "r"(b[0]), "r"(b[1]));
}
// Exact mask-split of two fp32 into bf16x2 hi (truncated) + bf16x2 lo (residual).
__device__ __forceinline__ void split2(float x, float y, uint32_t& hi, uint32_t& lo) {
    uint32_t xu = __float_as_uint(x), yu = __float_as_uint(y);
    hi = __byte_perm(xu, yu, 0x7632);
    float hx = __uint_as_float(xu & 0xFFFF0000u);
    float hy = __uint_as_float(yu & 0xFFFF0000u);
    __nv_bfloat162 l = __float22bfloat162_rn(make_float2(x - hx, y - hy));
    lo = reinterpret_cast<uint32_t&>(l);
}

// One K-chunk (32) of MMAs: 3 split terms, warp tile 32m x 64n, 96 HMMAs.
__device__ __forceinline__ void compute_chunk(uint32_t st, int wm, int wn, int lane,
                                              float (*d)[4]) {
    #pragma unroll
    for (int ks = 0; ks < 2; ks++) {
        uint32_t ar = (uint32_t)(wm * 32 + (lane & 15));
        uint32_t acu = (uint32_t)(ks * 2 + (lane >> 4));
        uint32_t ah[8], al[8];
        ldsm_x4(ah,     st + OFF_AHI + swz(ar, acu));
        ldsm_x4(ah + 4, st + OFF_AHI + swz(ar + 16, acu));
        ldsm_x4(al,     st + OFF_ALO + swz(ar, acu));
        ldsm_x4(al + 4, st + OFF_ALO + swz(ar + 16, acu));
        uint32_t brbase = (uint32_t)(wn * 64 + ((lane >> 4) & 1) * 8 + (lane & 7));
        uint32_t bcu = (uint32_t)(ks * 2 + ((lane >> 3) & 1));
        #pragma unroll
        for (int nt = 0; nt < 8; nt += 2) {
            uint32_t br = brbase + nt * 8;
            uint32_t bh[4], bl[4];
            ldsm_x4(bh, st + OFF_BHI + swz(br, bcu));
            ldsm_x4(bl, st + OFF_BLO + swz(br, bcu));
            mma16816(d[nt],         ah,     bh);
            mma16816(d[8 + nt],     ah + 4, bh);
            mma16816(d[nt + 1],     ah,     bh + 2);
            mma16816(d[8 + nt + 1], ah + 4, bh + 2);
            mma16816(d[nt],         ah,     bl);
            mma16816(d[8 + nt],     ah + 4, bl);
            mma16816(d[nt + 1],     ah,     bl + 2);
            mma16816(d[8 + nt + 1], ah + 4, bl + 2);
            mma16816(d[nt],         al,     bh);
            mma16816(d[8 + nt],     al + 4, bh);
            mma16816(d[nt + 1],     al,     bh + 2);
            mma16816(d[8 + nt + 1], al + 4, bh + 2);
        }
    }
}

// Issue one bf16 tile (128x32) via cp.async: thread t copies 2x16B of row t>>1.
__device__ __forceinline__ void issue_tile(uint32_t st_off, const __nv_bfloat16* src,
                                           size_t ld, int k0, int tid) {
    uint32_t row = (uint32_t)(tid >> 1);
    const __nv_bfloat16* s = src + (size_t)row * ld + k0;
    #pragma unroll
    for (int i = 0; i < 2; i++) {
        uint32_t cu = (uint32_t)((tid & 1) * 2 + i);
        CP16(st_off + swz(row, cu), s + cu * 8);
    }
}

// ---------------- elementwise split kernels ----------------
__global__ void split_kernel(const float* __restrict__ src, __nv_bfloat16* __restrict__ hi,
                             __nv_bfloat16* __restrict__ lo, size_t n) {
    size_t i = ((size_t)blockIdx.x * blockDim.x + threadIdx.x) * 4;
    if (i >= n) return;
    float4 v = *reinterpret_cast<const float4*>(src + i);
    uint32_t h0, l0, h1, l1;
    split2(v.x, v.y, h0, l0);
    split2(v.z, v.w, h1, l1);
    *reinterpret_cast<uint2*>(hi + i) = make_uint2(h0, h1);
    *reinterpret_cast<uint2*>(lo + i) = make_uint2(l0, l1);
}

// Transpose + split V: g_v[b][s][h] -> g_vthi/lo [b][h][s]
__global__ __launch_bounds__(256) void vsplitT_kernel() {
    __shared__ float ts[32][33];
    int h0 = blockIdx.x * 32, s0 = blockIdx.y * 32, b = blockIdx.z;
    int t = threadIdx.x;
    int sl = t >> 3, h4 = (t & 7) * 4;
    float4 v = *reinterpret_cast<const float4*>(
        g_v + ((size_t)b * SS + s0 + sl) * HH + h0 + h4);
    ts[sl][h4] = v.x; ts[sl][h4 + 1] = v.y; ts[sl][h4 + 2] = v.z; ts[sl][h4 + 3] = v.w;
    __syncthreads();
    int hr = t >> 3, s4 = (t & 7) * 4;
    uint32_t h0p, l0p, h1p, l1p;
    split2(ts[s4][hr], ts[s4 + 1][hr], h0p, l0p);
    split2(ts[s4 + 2][hr], ts[s4 + 3][hr], h1p, l1p);
    size_t o = ((size_t)b * HH + h0 + hr) * SS + s0 + s4;
    *reinterpret_cast<uint2*>(g_vthi + o) = make_uint2(h0p, h1p);
    *reinterpret_cast<uint2*>(g_vtlo + o) = make_uint2(l0p, l1p);
}

// ---------------- kernel 1: projections ----------------
__global__ __launch_bounds__(256, 2) void proj_hmma(const float* __restrict__ bias, int which) {
    extern __shared__ char sm[];
    uint32_t smb = smem_u32(sm);
    int tid = threadIdx.x, lane = tid & 31, wid = tid >> 5;
    int wm = wid & 3, wn = wid >> 2;
    int m0 = blockIdx.y * 128, n0 = blockIdx.x * 128;
    const __nv_bfloat16* Ahi = g_xhi + (size_t)m0 * HH;
    const __nv_bfloat16* Alo = g_xlo + (size_t)m0 * HH;
    const __nv_bfloat16* Bhi = g_whi[which] + (size_t)n0 * HH;
    const __nv_bfloat16* Blo = g_wlo[which] + (size_t)n0 * HH;

    float d[16][4];
    #pragma unroll
    for (int i = 0; i < 16; i++)
        #pragma unroll
        for (int j = 0; j < 4; j++) d[i][j] = 0.f;

    const int NC = HH / 32;
    #pragma unroll 1
    for (int p = 0; p < 2; p++) {  // prologue: stages 0,1
        uint32_t st = smb + p * STG_B;
        issue_tile(st + OFF_AHI, Ahi, HH, p * 32, tid);
        issue_tile(st + OFF_ALO, Alo, HH, p * 32, tid);
        issue_tile(st + OFF_BHI, Bhi, HH, p * 32, tid);
        issue_tile(st + OFF_BLO, Blo, HH, p * 32, tid);
        CP_COMMIT();
    }
    #pragma unroll 1
    for (int c = 0; c < NC; c++) {
        if (c + 1 < NC) CP_WAIT(1); else CP_WAIT(0);
        __syncthreads();
        if (c + 2 < NC) {
            uint32_t st = smb + ((c + 2) % NSTG) * STG_B;
            int k0 = (c + 2) * 32;
            issue_tile(st + OFF_AHI, Ahi, HH, k0, tid);
            issue_tile(st + OFF_ALO, Alo, HH, k0, tid);
            issue_tile(st + OFF_BHI, Bhi, HH, k0, tid);
            issue_tile(st + OFF_BLO, Blo, HH, k0, tid);
            CP_COMMIT();
        }
        compute_chunk(smb + (c % NSTG) * STG_B, wm, wn, lane, d);
    }

    int tq = lane >> 2, tr = lane & 3;
    if (which < 2) {  // write split bf16 q / k
        __nv_bfloat16* Chi = (which == 0) ? g_qhi : g_khi;
        __nv_bfloat16* Clo = (which == 0) ? g_qlo : g_klo;
        #pragma unroll
        for (int mt = 0; mt < 2; mt++)
            #pragma unroll
            for (int nt = 0; nt < 8; nt++) {
                int ml = wm * 32 + mt * 16 + tq;
                int n = n0 + wn * 64 + nt * 8 + tr * 2;
                float b0 = bias[n], b1 = bias[n + 1];
                float* dd = d[mt * 8 + nt];
                uint32_t h, l;
                split2(dd[0] + b0, dd[1] + b1, h, l);
                size_t o = (size_t)(m0 + ml) * HH + n;
                *reinterpret_cast<uint32_t*>(Chi + o) = h;
                *reinterpret_cast<uint32_t*>(Clo + o) = l;
                split2(dd[2] + b0, dd[3] + b1, h, l);
                o += 8 * HH;
                *reinterpret_cast<uint32_t*>(Chi + o) = h;
                *reinterpret_cast<uint32_t*>(Clo + o) = l;
            }
    } else {  // v as fp32 (transposed+split later)
        #pragma unroll
        for (int mt = 0; mt < 2; mt++)
            #pragma unroll
            for (int nt = 0; nt < 8; nt++) {
                int ml = wm * 32 + mt * 16 + tq;
                int n = n0 + wn * 64 + nt * 8 + tr * 2;
                float* dd = d[mt * 8 + nt];
                *reinterpret_cast<float2*>(g_v + (size_t)(m0 + ml) * HH + n) =
                    make_float2(dd[0], dd[1]);
                *reinterpret_cast<float2*>(g_v + (size_t)(m0 + ml + 8) * HH + n) =
                    make_float2(dd[2], dd[3]);
            }
    }
}

// ---------------- kernel 2: windowed decayed scores ----------------
__global__ __launch_bounds__(256, 2) void score_hmma() {
    int w = blockIdx.x, qt = blockIdx.y, b = blockIdx.z;
    int i0 = qt * 128, j0 = i0 + (w - (NW - 1)) * 128;
    int tid = threadIdx.x, lane = tid & 31, wid = tid >> 5;
    size_t tile = ((size_t)(b * QT + qt)) * 128 * WK;

    if (j0 < 0) {
        for (int i = tid; i < 128 * 16; i += 256) {
            int row = i >> 4, q = i & 15;
            size_t o = tile + (size_t)row * WK + w * 128 + q * 8;
            *reinterpret_cast<uint4*>(g_shi + o) = make_uint4(0, 0, 0, 0);
            *reinterpret_cast<uint4*>(g_slo + o) = make_uint4(0, 0, 0, 0);
        }
        return;
    }

    extern __shared__ char sm[];
    uint32_t smb = smem_u32(sm);
    int wm = wid & 3, wn = wid >> 2;
    const __nv_bfloat16* Ahi = g_qhi + ((size_t)b * SS + i0) * HH;
    const __nv_bfloat16* Alo = g_qlo + ((size_t)b * SS + i0) * HH;
    const __nv_bfloat16* Bhi = g_khi + ((size_t)b * SS + j0) * HH;
    const __nv_bfloat16* Blo = g_klo + ((size_t)b * SS + j0) * HH;

    float d[16][4];
    #pragma unroll
    for (int i = 0; i < 16; i++)
        #pragma unroll
        for (int j = 0; j < 4; j++) d[i][j] = 0.f;

    const int NC = HH / 32;
    #pragma unroll 1
    for (int p = 0; p < 2; p++) {
        uint32_t st = smb + p * STG_B;
        issue_tile(st + OFF_AHI, Ahi, HH, p * 32, tid);
        issue_tile(st + OFF_ALO, Alo, HH, p * 32, tid);
        issue_tile(st + OFF_BHI, Bhi, HH, p * 32, tid);
        issue_tile(st + OFF_BLO, Blo, HH, p * 32, tid);
        CP_COMMIT();
    }
    #pragma unroll 1
    for (int c = 0; c < NC; c++) {
        if (c + 1 < NC) CP_WAIT(1); else CP_WAIT(0);
        __syncthreads();
        if (c + 2 < NC) {
            uint32_t st = smb + ((c + 2) % NSTG) * STG_B;
            int k0 = (c + 2) * 32;
            issue_tile(st + OFF_AHI, Ahi, HH, k0, tid);
            issue_tile(st + OFF_ALO, Alo, HH, k0, tid);
            issue_tile(st + OFF_BHI, Bhi, HH, k0, tid);
            issue_tile(st + OFF_BLO, Blo, HH, k0, tid);
            CP_COMMIT();
        }
        compute_chunk(smb + (c % NSTG) * STG_B, wm, wn, lane, d);
    }

    int tq = lane >> 2, tr = lane & 3;
    #pragma unroll
    for (int mt = 0; mt < 2; mt++)
        #pragma unroll
        for (int nt = 0; nt < 8; nt++) {
            int ncol = wn * 64 + nt * 8 + tr * 2;
            float* dd = d[mt * 8 + nt];
            #pragma unroll
            for (int half = 0; half < 2; half++) {
                int ml = wm * 32 + mt * 16 + tq + half * 8;
                int i = i0 + ml;
                int d0 = i - (j0 + ncol), d1 = i - (j0 + ncol + 1);
                float w0 = (d0 < 0) ? 0.f : exp2f(LOG2G * (float)d0);
                float w1 = (d1 < 0) ? 0.f : exp2f(LOG2G * (float)d1);
                uint32_t h, l;
                split2(dd[half * 2 + 0] * w0, dd[half * 2 + 1] * w1, h, l);
                size_t o = tile + (size_t)ml * WK + w * 128 + ncol;
                *reinterpret_cast<uint32_t*>(g_shi + o) = h;
                *reinterpret_cast<uint32_t*>(g_slo + o) = l;
            }
        }
}

// ---------------- kernel 3: banded output GEMM O = S * V ----------------
__global__ __launch_bounds__(256, 2) void out_hmma(float* __restrict__ out) {
    int nc = blockIdx.x, qt = blockIdx.y, b = blockIdx.z;
    int i0 = qt * 128, n0 = nc * 128, jbase = i0 - (NW - 1) * 128;
    int tid = threadIdx.x, lane = tid & 31, wid = tid >> 5;
    int wm = wid & 3, wn = wid >> 2;
    size_t tile = ((size_t)(b * QT + qt)) * 128 * WK;
    const __nv_bfloat16* Ahi = g_shi + tile;
    const __nv_bfloat16* Alo = g_slo + tile;
    const __nv_bfloat16* Vth = g_vthi + ((size_t)b * HH + n0) * SS;
    const __nv_bfloat16* Vtl = g_vtlo + ((size_t)b * HH + n0) * SS;

    extern __shared__ char sm[];
    uint32_t smb = smem_u32(sm);

    float d[16][4];
    #pragma unroll
    for (int i = 0; i < 16; i++)
        #pragma unroll
        for (int j = 0; j < 4; j++) d[i][j] = 0.f;

    // B tile issue with left-edge clamp (S is zero for j<0 so values don't matter)
    auto issue_vt = [&](uint32_t st, int k0) {
        uint32_t row = (uint32_t)(tid >> 1);
        #pragma unroll
        for (int i = 0; i < 2; i++) {
            uint32_t cu = (uint32_t)((tid & 1) * 2 + i);
            int j = jbase + k0 + (int)cu * 8;
            if (j < 0) j = 0;
            CP16(st + OFF_BHI + swz(row, cu), Vth + (size_t)row * SS + j);
            CP16(st + OFF_BLO + swz(row, cu), Vtl + (size_t)row * SS + j);
        }
    };

    const int NC = WK / 32;  // 20
    #pragma unroll 1
    for (int p = 0; p < 2; p++) {
        uint32_t st = smb + p * STG_B;
        issue_tile(st + OFF_AHI, Ahi, WK, p * 32, tid);
        issue_tile(st + OFF_ALO, Alo, WK, p * 32, tid);
        issue_vt(st, p * 32);
        CP_COMMIT();
    }
    #pragma unroll 1
    for (int c = 0; c < NC; c++) {
        if (c + 1 < NC) CP_WAIT(1); else CP_WAIT(0);
        __syncthreads();
        if (c + 2 < NC) {
            uint32_t st = smb + ((c + 2) % NSTG) * STG_B;
            int k0 = (c + 2) * 32;
            issue_tile(st + OFF_AHI, Ahi, WK, k0, tid);
            issue_tile(st + OFF_ALO, Alo, WK, k0, tid);
            issue_vt(st, k0);
            CP_COMMIT();
        }
        compute_chunk(smb + (c % NSTG) * STG_B, wm, wn, lane, d);
    }

    int tq = lane >> 2, tr = lane & 3;
    #pragma unroll
    for (int mt = 0; mt < 2; mt++)
        #pragma unroll
        for (int nt = 0; nt < 8; nt++) {
            int ml = wm * 32 + mt * 16 + tq;
            int n = n0 + wn * 64 + nt * 8 + tr * 2;
            float* dd = d[mt * 8 + nt];
            *reinterpret_cast<float2*>(out + ((size_t)b * SS + i0 + ml) * HH + n) =
                make_float2(dd[0], dd[1]);
            *reinterpret_cast<float2*>(out + ((size_t)b * SS + i0 + ml + 8) * HH + n) =
                make_float2(dd[2], dd[3]);
        }
}

// ---------------- host launcher ----------------
extern "C" void kernel_launch(void* const* d_in, const int* in_sizes, int n_in,
                              void* d_out, int out_size) {
    const float* x  = (const float*)d_in[0];
    const float* Wq = (const float*)d_in[1];
    const float* bq = (const float*)d_in[2];
    const float* Wk = (const float*)d_in[3];
    const float* bk = (const float*)d_in[4];
    const float* Wv = (const float*)d_in[5];
    float* out = (float*)d_out;

    cudaFuncSetAttribute(proj_hmma, cudaFuncAttributeMaxDynamicSharedMemorySize, SMEM_TOTAL);
    cudaFuncSetAttribute(score_hmma, cudaFuncAttributeMaxDynamicSharedMemorySize, SMEM_TOTAL);
    cudaFuncSetAttribute(out_hmma, cudaFuncAttributeMaxDynamicSharedMemorySize, SMEM_TOTAL);

    __nv_bfloat16 *xhi, *xlo, *whi0, *wlo0, *whi1, *wlo1, *whi2, *wlo2;
    cudaGetSymbolAddress((void**)&xhi, g_xhi);
    cudaGetSymbolAddress((void**)&xlo, g_xlo);
    cudaGetSymbolAddress((void**)&whi0, g_whi);
    cudaGetSymbolAddress((void**)&wlo0, g_wlo);
    whi1 = whi0 + (size_t)HH * HH; whi2 = whi1 + (size_t)HH * HH;
    wlo1 = wlo0 + (size_t)HH * HH; wlo2 = wlo1 + (size_t)HH * HH;

    size_t nx = (size_t)MT * HH, nw = (size_t)HH * HH;
    split_kernel<<<(unsigned)(nx / 4 / 256), 256>>>(x, xhi, xlo, nx);
    split_kernel<<<(unsigned)(nw / 4 / 256), 256>>>(Wq, whi0, wlo0, nw);
    split_kernel<<<(unsigned)(nw / 4 / 256), 256>>>(Wk, whi1, wlo1, nw);
    split_kernel<<<(unsigned)(nw / 4 / 256), 256>>>(Wv, whi2, wlo2, nw);

    dim3 gproj(HH / 128, MT / 128);
    proj_hmma<<<gproj, 256, SMEM_TOTAL>>>(bq, 0);
    proj_hmma<<<gproj, 256, SMEM_TOTAL>>>(bk, 1);
    proj_hmma<<<gproj, 256, SMEM_TOTAL>>>(nullptr, 2);

    dim3 gvt(HH / 32, SS / 32, BB);
    vsplitT_kernel<<<gvt, 256>>>();

    dim3 gscore(NW, QT, BB);
    score_hmma<<<gscore, 256, SMEM_TOTAL>>>();

    dim3 gout(HH / 128, QT, BB);
    out_hmma<<<gout, 256, SMEM_TOTAL>>>(out);
}

// round 5
// speedup vs baseline: 3.2886x; 1.1954x over previous
#include <cuda_runtime.h>
#include <cuda_bf16.h>
#include <stdint.h>

// ---------------- problem constants ----------------
#define BB 4
#define SS 4096
#define HH 1024
#define MT (BB * SS)
#define QT 32
#define NW 5
#define WK 640
#define LOG2G (-0.04580368961312758f)

// ---------------- smem layout: XOR-swizzled 64B rows ----------------
#define OFF_AHI 0
#define OFF_ALO 8192
#define OFF_BHI 16384
#define OFF_BLO 24576
#define STG_B 32768
#define NSTG 3
#define SMEM_TOTAL (NSTG * STG_B)  // 98304

// ---------------- device scratch ----------------
__device__ __align__(16) __nv_bfloat16 g_xhi[(size_t)MT * HH];
__device__ __align__(16) __nv_bfloat16 g_xlo[(size_t)MT * HH];
__device__ __align__(16) __nv_bfloat16 g_whi[3][(size_t)HH * HH];
__device__ __align__(16) __nv_bfloat16 g_wlo[3][(size_t)HH * HH];
__device__ __align__(16) __nv_bfloat16 g_qhi[(size_t)MT * HH];
__device__ __align__(16) __nv_bfloat16 g_qlo[(size_t)MT * HH];
__device__ __align__(16) __nv_bfloat16 g_khi[(size_t)MT * HH];
__device__ __align__(16) __nv_bfloat16 g_klo[(size_t)MT * HH];
__device__ __align__(16) float g_v[(size_t)MT * HH];
__device__ __align__(16) __nv_bfloat16 g_vthi[(size_t)MT * HH];  // [b][h][s]
__device__ __align__(16) __nv_bfloat16 g_vtlo[(size_t)MT * HH];
__device__ __align__(16) __nv_bfloat16 g_shi[(size_t)BB * QT * 128 * WK];
__device__ __align__(16) __nv_bfloat16 g_slo[(size_t)BB * QT * 128 * WK];

// ---------------- helpers ----------------
__device__ __forceinline__ uint32_t smem_u32(const void* p) {
    uint32_t a;
    asm("{ .reg .u64 t; cvta.to.shared.u64 t, %1; cvt.u32.u64 %0, t; }"
        : "=r"(a) : "l"(p));
    return a;
}
__device__ __forceinline__ uint32_t swz(uint32_t row, uint32_t cu) {
    return row * 64u + ((cu ^ ((row >> 1) & 3u)) << 4);
}
#define CP16(dst, src) \
    asm volatile("cp.async.cg.shared.global [%0], [%1], 16;" :: "r"(dst), "l"(src))
#define CP_COMMIT() asm volatile("cp.async.commit_group;" ::: "memory")
#define CP_WAIT(n)  asm volatile("cp.async.wait_group %0;" :: "n"(n) : "memory")

__device__ __forceinline__ void ldsm_x4(uint32_t* r, uint32_t addr) {
    asm volatile("ldmatrix.sync.aligned.m8n8.x4.shared.b16 {%0,%1,%2,%3}, [%4];"
                 : "=r"(r[0]), "=r"(r[1]), "=r"(r[2]), "=r"(r[3]) : "r"(addr));
}
__device__ __forceinline__ void mma16816(float* d, const uint32_t* a, const uint32_t* b) {
    asm volatile(
        "mma.sync.aligned.m16n8k16.row.col.f32.bf16.bf16.f32 "
        "{%0,%1,%2,%3}, {%4,%5,%6,%7}, {%8,%9}, {%0,%1,%2,%3};"
        : "+f"(d[0]), "+f"(d[1]), "+f"(d[2]), "+f"(d[3])
        : "r"(a[0]), "r"(a[1]), "r"(a[2]), "r"(a[3]), "r"(b[0]), "r"(b[1]));
}
// Exact mask-split of two fp32 into bf16x2 hi (truncated) + bf16x2 lo (residual).
__device__ __forceinline__ void split2(float x, float y, uint32_t& hi, uint32_t& lo) {
    uint32_t xu = __float_as_uint(x), yu = __float_as_uint(y);
    hi = __byte_perm(xu, yu, 0x7632);
    float hx = __uint_as_float(xu & 0xFFFF0000u);
    float hy = __uint_as_float(yu & 0xFFFF0000u);
    __nv_bfloat162 l = __float22bfloat162_rn(make_float2(x - hx, y - hy));
    lo = reinterpret_cast<uint32_t&>(l);
}

// One K-chunk (32) of MMAs: 3 split terms, warp tile 64m x 64n, 192 HMMAs.
// d indexed [mt*8+nt][4], mt in 0..3 (m16 tiles), nt in 0..7 (n8 tiles).
__device__ __forceinline__ void compute_chunk(uint32_t st, int wm, int wn, int lane,
                                              float (*d)[4]) {
    #pragma unroll
    for (int ks = 0; ks < 2; ks++) {
        uint32_t ah[16], al[16], bh[16], bl[16];
        uint32_t ar = (uint32_t)(wm * 64 + (lane & 15));
        uint32_t acu = (uint32_t)(ks * 2 + (lane >> 4));
        #pragma unroll
        for (int mt = 0; mt < 4; mt++) {
            ldsm_x4(ah + 4 * mt, st + OFF_AHI + swz(ar + 16 * mt, acu));
            ldsm_x4(al + 4 * mt, st + OFF_ALO + swz(ar + 16 * mt, acu));
        }
        uint32_t br = (uint32_t)(wn * 64 + ((lane >> 4) & 1) * 8 + (lane & 7));
        uint32_t bcu = (uint32_t)(ks * 2 + ((lane >> 3) & 1));
        #pragma unroll
        for (int nt = 0; nt < 8; nt += 2) {
            ldsm_x4(bh + 2 * nt, st + OFF_BHI + swz(br + 8 * nt, bcu));
            ldsm_x4(bl + 2 * nt, st + OFF_BLO + swz(br + 8 * nt, bcu));
        }
        #pragma unroll
        for (int nt = 0; nt < 8; nt++) {
            #pragma unroll
            for (int mt = 0; mt < 4; mt++) mma16816(d[mt * 8 + nt], ah + 4 * mt, bh + 2 * nt);
            #pragma unroll
            for (int mt = 0; mt < 4; mt++) mma16816(d[mt * 8 + nt], ah + 4 * mt, bl + 2 * nt);
            #pragma unroll
            for (int mt = 0; mt < 4; mt++) mma16816(d[mt * 8 + nt], al + 4 * mt, bh + 2 * nt);
        }
    }
}

// Issue one bf16 tile (128 rows x 32 k) via cp.async, 128 threads.
__device__ __forceinline__ void issue_tile(uint32_t dst, const __nv_bfloat16* src,
                                           size_t ld, int k0, int tid) {
    uint32_t row = (uint32_t)(tid >> 2), cu = (uint32_t)(tid & 3);
    #pragma unroll
    for (int h = 0; h < 4; h++) {
        uint32_t r = row + 32 * h;
        CP16(dst + swz(r, cu), src + (size_t)r * ld + k0 + cu * 8);
    }
}

// ---------------- elementwise split kernels ----------------
__global__ void split_kernel(const float* __restrict__ src, __nv_bfloat16* __restrict__ hi,
                             __nv_bfloat16* __restrict__ lo, size_t n) {
    size_t i = ((size_t)blockIdx.x * blockDim.x + threadIdx.x) * 4;
    if (i >= n) return;
    float4 v = *reinterpret_cast<const float4*>(src + i);
    uint32_t h0, l0, h1, l1;
    split2(v.x, v.y, h0, l0);
    split2(v.z, v.w, h1, l1);
    *reinterpret_cast<uint2*>(hi + i) = make_uint2(h0, h1);
    *reinterpret_cast<uint2*>(lo + i) = make_uint2(l0, l1);
}

// Transpose + split V: g_v[b][s][h] -> g_vthi/lo [b][h][s]
__global__ __launch_bounds__(256) void vsplitT_kernel() {
    __shared__ float ts[32][33];
    int h0 = blockIdx.x * 32, s0 = blockIdx.y * 32, b = blockIdx.z;
    int t = threadIdx.x;
    int sl = t >> 3, h4 = (t & 7) * 4;
    float4 v = *reinterpret_cast<const float4*>(
        g_v + ((size_t)b * SS + s0 + sl) * HH + h0 + h4);
    ts[sl][h4] = v.x; ts[sl][h4 + 1] = v.y; ts[sl][h4 + 2] = v.z; ts[sl][h4 + 3] = v.w;
    __syncthreads();
    int hr = t >> 3, s4 = (t & 7) * 4;
    uint32_t h0p, l0p, h1p, l1p;
    split2(ts[s4][hr], ts[s4 + 1][hr], h0p, l0p);
    split2(ts[s4 + 2][hr], ts[s4 + 3][hr], h1p, l1p);
    size_t o = ((size_t)b * HH + h0 + hr) * SS + s0 + s4;
    *reinterpret_cast<uint2*>(g_vthi + o) = make_uint2(h0p, h1p);
    *reinterpret_cast<uint2*>(g_vtlo + o) = make_uint2(l0p, l1p);
}

// ---------------- kernel 1: projections ----------------
__global__ __launch_bounds__(128, 2) void proj_hmma(const float* __restrict__ bias, int which) {
    extern __shared__ char sm[];
    uint32_t smb = smem_u32(sm);
    int tid = threadIdx.x, lane = tid & 31, wid = tid >> 5;
    int wm = wid & 1, wn = wid >> 1;
    int m0 = blockIdx.y * 128, n0 = blockIdx.x * 128;
    const __nv_bfloat16* Ahi = g_xhi + (size_t)m0 * HH;
    const __nv_bfloat16* Alo = g_xlo + (size_t)m0 * HH;
    const __nv_bfloat16* Bhi = g_whi[which] + (size_t)n0 * HH;
    const __nv_bfloat16* Blo = g_wlo[which] + (size_t)n0 * HH;

    float d[32][4];
    #pragma unroll
    for (int i = 0; i < 32; i++)
        #pragma unroll
        for (int j = 0; j < 4; j++) d[i][j] = 0.f;

    const int NC = HH / 32;
    #pragma unroll 1
    for (int p = 0; p < 2; p++) {
        uint32_t st = smb + p * STG_B;
        issue_tile(st + OFF_AHI, Ahi, HH, p * 32, tid);
        issue_tile(st + OFF_ALO, Alo, HH, p * 32, tid);
        issue_tile(st + OFF_BHI, Bhi, HH, p * 32, tid);
        issue_tile(st + OFF_BLO, Blo, HH, p * 32, tid);
        CP_COMMIT();
    }
    #pragma unroll 1
    for (int c = 0; c < NC; c++) {
        if (c + 1 < NC) CP_WAIT(1); else CP_WAIT(0);
        __syncthreads();
        if (c + 2 < NC) {
            uint32_t st = smb + ((c + 2) % NSTG) * STG_B;
            int k0 = (c + 2) * 32;
            issue_tile(st + OFF_AHI, Ahi, HH, k0, tid);
            issue_tile(st + OFF_ALO, Alo, HH, k0, tid);
            issue_tile(st + OFF_BHI, Bhi, HH, k0, tid);
            issue_tile(st + OFF_BLO, Blo, HH, k0, tid);
            CP_COMMIT();
        }
        compute_chunk(smb + (c % NSTG) * STG_B, wm, wn, lane, d);
    }

    int tq = lane >> 2, tr = lane & 3;
    if (which < 2) {
        __nv_bfloat16* Chi = (which == 0) ? g_qhi : g_khi;
        __nv_bfloat16* Clo = (which == 0) ? g_qlo : g_klo;
        #pragma unroll
        for (int mt = 0; mt < 4; mt++)
            #pragma unroll
            for (int nt = 0; nt < 8; nt++) {
                int ml = wm * 64 + mt * 16 + tq;
                int n = n0 + wn * 64 + nt * 8 + tr * 2;
                float b0 = bias[n], b1 = bias[n + 1];
                float* dd = d[mt * 8 + nt];
                uint32_t h, l;
                split2(dd[0] + b0, dd[1] + b1, h, l);
                size_t o = (size_t)(m0 + ml) * HH + n;
                *reinterpret_cast<uint32_t*>(Chi + o) = h;
                *reinterpret_cast<uint32_t*>(Clo + o) = l;
                split2(dd[2] + b0, dd[3] + b1, h, l);
                o += 8 * HH;
                *reinterpret_cast<uint32_t*>(Chi + o) = h;
                *reinterpret_cast<uint32_t*>(Clo + o) = l;
            }
    } else {
        #pragma unroll
        for (int mt = 0; mt < 4; mt++)
            #pragma unroll
            for (int nt = 0; nt < 8; nt++) {
                int ml = wm * 64 + mt * 16 + tq;
                int n = n0 + wn * 64 + nt * 8 + tr * 2;
                float* dd = d[mt * 8 + nt];
                *reinterpret_cast<float2*>(g_v + (size_t)(m0 + ml) * HH + n) =
                    make_float2(dd[0], dd[1]);
                *reinterpret_cast<float2*>(g_v + (size_t)(m0 + ml + 8) * HH + n) =
                    make_float2(dd[2], dd[3]);
            }
    }
}

// ---------------- kernel 2: windowed decayed scores ----------------
__global__ __launch_bounds__(128, 2) void score_hmma() {
    int w = blockIdx.x, qt = blockIdx.y, b = blockIdx.z;
    int i0 = qt * 128, j0 = i0 + (w - (NW - 1)) * 128;
    int tid = threadIdx.x, lane = tid & 31, wid = tid >> 5;
    size_t tile = ((size_t)(b * QT + qt)) * 128 * WK;

    if (j0 < 0) {
        for (int i = tid; i < 128 * 16; i += 128) {
            int row = i >> 4, q = i & 15;
            size_t o = tile + (size_t)row * WK + w * 128 + q * 8;
            *reinterpret_cast<uint4*>(g_shi + o) = make_uint4(0, 0, 0, 0);
            *reinterpret_cast<uint4*>(g_slo + o) = make_uint4(0, 0, 0, 0);
        }
        return;
    }

    extern __shared__ char sm[];
    uint32_t smb = smem_u32(sm);
    int wm = wid & 1, wn = wid >> 1;
    const __nv_bfloat16* Ahi = g_qhi + ((size_t)b * SS + i0) * HH;
    const __nv_bfloat16* Alo = g_qlo + ((size_t)b * SS + i0) * HH;
    const __nv_bfloat16* Bhi = g_khi + ((size_t)b * SS + j0) * HH;
    const __nv_bfloat16* Blo = g_klo + ((size_t)b * SS + j0) * HH;

    float d[32][4];
    #pragma unroll
    for (int i = 0; i < 32; i++)
        #pragma unroll
        for (int j = 0; j < 4; j++) d[i][j] = 0.f;

    const int NC = HH / 32;
    #pragma unroll 1
    for (int p = 0; p < 2; p++) {
        uint32_t st = smb + p * STG_B;
        issue_tile(st + OFF_AHI, Ahi, HH, p * 32, tid);
        issue_tile(st + OFF_ALO, Alo, HH, p * 32, tid);
        issue_tile(st + OFF_BHI, Bhi, HH, p * 32, tid);
        issue_tile(st + OFF_BLO, Blo, HH, p * 32, tid);
        CP_COMMIT();
    }
    #pragma unroll 1
    for (int c = 0; c < NC; c++) {
        if (c + 1 < NC) CP_WAIT(1); else CP_WAIT(0);
        __syncthreads();
        if (c + 2 < NC) {
            uint32_t st = smb + ((c + 2) % NSTG) * STG_B;
            int k0 = (c + 2) * 32;
            issue_tile(st + OFF_AHI, Ahi, HH, k0, tid);
            issue_tile(st + OFF_ALO, Alo, HH, k0, tid);
            issue_tile(st + OFF_BHI, Bhi, HH, k0, tid);
            issue_tile(st + OFF_BLO, Blo, HH, k0, tid);
            CP_COMMIT();
        }
        compute_chunk(smb + (c % NSTG) * STG_B, wm, wn, lane, d);
    }

    int tq = lane >> 2, tr = lane & 3;
    #pragma unroll
    for (int mt = 0; mt < 4; mt++)
        #pragma unroll
        for (int nt = 0; nt < 8; nt++) {
            int ncol = wn * 64 + nt * 8 + tr * 2;
            float* dd = d[mt * 8 + nt];
            #pragma unroll
            for (int half = 0; half < 2; half++) {
                int ml = wm * 64 + mt * 16 + tq + half * 8;
                int i = i0 + ml;
                int d0 = i - (j0 + ncol), d1 = i - (j0 + ncol + 1);
                float w0 = (d0 < 0) ? 0.f : exp2f(LOG2G * (float)d0);
                float w1 = (d1 < 0) ? 0.f : exp2f(LOG2G * (float)d1);
                uint32_t h, l;
                split2(dd[half * 2 + 0] * w0, dd[half * 2 + 1] * w1, h, l);
                size_t o = tile + (size_t)ml * WK + w * 128 + ncol;
                *reinterpret_cast<uint32_t*>(g_shi + o) = h;
                *reinterpret_cast<uint32_t*>(g_slo + o) = l;
            }
        }
}

// ---------------- kernel 3: banded output GEMM O = S * V ----------------
__global__ __launch_bounds__(128, 2) void out_hmma(float* __restrict__ out) {
    int nc = blockIdx.x, qt = blockIdx.y, b = blockIdx.z;
    int i0 = qt * 128, n0 = nc * 128, jbase = i0 - (NW - 1) * 128;
    int tid = threadIdx.x, lane = tid & 31, wid = tid >> 5;
    int wm = wid & 1, wn = wid >> 1;
    size_t tile = ((size_t)(b * QT + qt)) * 128 * WK;
    const __nv_bfloat16* Ahi = g_shi + tile;
    const __nv_bfloat16* Alo = g_slo + tile;
    const __nv_bfloat16* Vth = g_vthi + ((size_t)b * HH + n0) * SS;
    const __nv_bfloat16* Vtl = g_vtlo + ((size_t)b * HH + n0) * SS;

    extern __shared__ char sm[];
    uint32_t smb = smem_u32(sm);

    float d[32][4];
    #pragma unroll
    for (int i = 0; i < 32; i++)
        #pragma unroll
        for (int j = 0; j < 4; j++) d[i][j] = 0.f;

    auto issue_vt = [&](uint32_t st, int k0) {
        uint32_t row = (uint32_t)(tid >> 2), cu = (uint32_t)(tid & 3);
        int j = jbase + k0 + (int)cu * 8;
        if (j < 0) j = 0;  // S is zero there; value irrelevant
        #pragma unroll
        for (int h = 0; h < 4; h++) {
            uint32_t r = row + 32 * h;
            CP16(st + OFF_BHI + swz(r, cu), Vth + (size_t)r * SS + j);
            CP16(st + OFF_BLO + swz(r, cu), Vtl + (size_t)r * SS + j);
        }
    };

    const int NC = WK / 32;  // 20
    #pragma unroll 1
    for (int p = 0; p < 2; p++) {
        uint32_t st = smb + p * STG_B;
        issue_tile(st + OFF_AHI, Ahi, WK, p * 32, tid);
        issue_tile(st + OFF_ALO, Alo, WK, p * 32, tid);
        issue_vt(st, p * 32);
        CP_COMMIT();
    }
    #pragma unroll 1
    for (int c = 0; c < NC; c++) {
        if (c + 1 < NC) CP_WAIT(1); else CP_WAIT(0);
        __syncthreads();
        if (c + 2 < NC) {
            uint32_t st = smb + ((c + 2) % NSTG) * STG_B;
            int k0 = (c + 2) * 32;
            issue_tile(st + OFF_AHI, Ahi, WK, k0, tid);
            issue_tile(st + OFF_ALO, Alo, WK, k0, tid);
            issue_vt(st, k0);
            CP_COMMIT();
        }
        compute_chunk(smb + (c % NSTG) * STG_B, wm, wn, lane, d);
    }

    int tq = lane >> 2, tr = lane & 3;
    #pragma unroll
    for (int mt = 0; mt < 4; mt++)
        #pragma unroll
        for (int nt = 0; nt < 8; nt++) {
            int ml = wm * 64 + mt * 16 + tq;
            int n = n0 + wn * 64 + nt * 8 + tr * 2;
            float* dd = d[mt * 8 + nt];
            *reinterpret_cast<float2*>(out + ((size_t)b * SS + i0 + ml) * HH + n) =
                make_float2(dd[0], dd[1]);
            *reinterpret_cast<float2*>(out + ((size_t)b * SS + i0 + ml + 8) * HH + n) =
                make_float2(dd[2], dd[3]);
        }
}

// ---------------- host launcher ----------------
extern "C" void kernel_launch(void* const* d_in, const int* in_sizes, int n_in,
                              void* d_out, int out_size) {
    const float* x  = (const float*)d_in[0];
    const float* Wq = (const float*)d_in[1];
    const float* bq = (const float*)d_in[2];
    const float* Wk = (const float*)d_in[3];
    const float* bk = (const float*)d_in[4];
    const float* Wv = (const float*)d_in[5];
    float* out = (float*)d_out;

    cudaFuncSetAttribute(proj_hmma, cudaFuncAttributeMaxDynamicSharedMemorySize, SMEM_TOTAL);
    cudaFuncSetAttribute(score_hmma, cudaFuncAttributeMaxDynamicSharedMemorySize, SMEM_TOTAL);
    cudaFuncSetAttribute(out_hmma, cudaFuncAttributeMaxDynamicSharedMemorySize, SMEM_TOTAL);

    __nv_bfloat16 *xhi, *xlo, *whi0, *wlo0, *whi1, *wlo1, *whi2, *wlo2;
    cudaGetSymbolAddress((void**)&xhi, g_xhi);
    cudaGetSymbolAddress((void**)&xlo, g_xlo);
    cudaGetSymbolAddress((void**)&whi0, g_whi);
    cudaGetSymbolAddress((void**)&wlo0, g_wlo);
    whi1 = whi0 + (size_t)HH * HH; whi2 = whi1 + (size_t)HH * HH;
    wlo1 = wlo0 + (size_t)HH * HH; wlo2 = wlo1 + (size_t)HH * HH;

    size_t nx = (size_t)MT * HH, nw = (size_t)HH * HH;
    split_kernel<<<(unsigned)(nx / 4 / 256), 256>>>(x, xhi, xlo, nx);
    split_kernel<<<(unsigned)(nw / 4 / 256), 256>>>(Wq, whi0, wlo0, nw);
    split_kernel<<<(unsigned)(nw / 4 / 256), 256>>>(Wk, whi1, wlo1, nw);
    split_kernel<<<(unsigned)(nw / 4 / 256), 256>>>(Wv, whi2, wlo2, nw);

    dim3 gproj(HH / 128, MT / 128);
    proj_hmma<<<gproj, 128, SMEM_TOTAL>>>(bq, 0);
    proj_hmma<<<gproj, 128, SMEM_TOTAL>>>(bk, 1);
    proj_hmma<<<gproj, 128, SMEM_TOTAL>>>(nullptr, 2);

    dim3 gvt(HH / 32, SS / 32, BB);
    vsplitT_kernel<<<gvt, 256>>>();

    dim3 gscore(NW, QT, BB);
    score_hmma<<<gscore, 128, SMEM_TOTAL>>>();

    dim3 gout(HH / 128, QT, BB);
    out_hmma<<<gout, 128, SMEM_TOTAL>>>(out);
}